// round 11
// baseline (speedup 1.0000x reference)
#include <cuda_runtime.h>
#include <cuda_fp16.h>

#define B_   8
#define TE_  512
#define TD_  128
#define H_   256
#define ESPLIT 4

// Scratch (allocation-free rule: device globals)
__device__ float g_ep[B_ * TE_ * H_];      // enc @ W_a   [B,TE,H]
__device__ float g_dp[B_ * TD_ * H_];      // dec @ U_a   [B,TD,H]
__device__ float g_score[B_ * TD_ * TE_];  // raw scores -> weights (in place)
__device__ float g_part[ESPLIT][B_ * TD_ * H_];  // ctx partial sums (4 MB)

__device__ __forceinline__ __half2 tanh2_fast(__half2 x2) {
    unsigned y2;
    asm("tanh.approx.f16x2 %0, %1;" : "=r"(y2) : "r"(*(unsigned*)&x2));
    return *(__half2*)&y2;
}

// Packed fp32 pair FMA (Blackwell FFMA2): d = a*b + d, two lanes at once.
__device__ __forceinline__ void ffma2(unsigned long long& d,
                                      unsigned long long a,
                                      unsigned long long b) {
    asm("fma.rn.f32x2 %0, %1, %2, %0;" : "+l"(d) : "l"(a), "l"(b));
}
__device__ __forceinline__ unsigned long long rep2(float x) {
    unsigned long long p;
    asm("mov.b64 %0, {%1, %1};" : "=l"(p) : "r"(__float_as_uint(x)));
    return p;
}
__device__ __forceinline__ void unpk2(unsigned long long v,
                                      float& lo, float& hi) {
    unsigned a, b;
    asm("mov.b64 {%0, %1}, %2;" : "=r"(a), "=r"(b) : "l"(v));
    lo = __uint_as_float(a);
    hi = __uint_as_float(b);
}
__device__ __forceinline__ unsigned packh2(float a, float b) {
    __half2 h = __floats2half2_rn(a, b);   // lo = a, hi = b
    return *(unsigned*)&h;
}

// ---------------------------------------------------------------------------
// Projection GEMM, FFMA2 edition. (unchanged)
// BM=64, BN=32, BK=16, 128 threads. Blocks [0,512)=enc@Wa, [512,640)=dec@Ua.
// ---------------------------------------------------------------------------
__global__ __launch_bounds__(128) void proj_kernel(
    const float* __restrict__ enc, const float* __restrict__ dec,
    const float* __restrict__ Wa,  const float* __restrict__ Ua)
{
    __shared__ float As[16][68];
    __shared__ float Ws[16][36];

    const int bid = blockIdx.x;
    const float* __restrict__ A;
    const float* __restrict__ W;
    float* __restrict__ P;
    int bm, bn;
    if (bid < 512) {
        A = enc; W = Wa; P = g_ep;
        bm = (bid >> 3) * 64; bn = (bid & 7) * 32;
    } else {
        const int r = bid - 512;
        A = dec; W = Ua; P = g_dp;
        bm = (r >> 3) * 64; bn = (r & 7) * 32;
    }

    const int t  = threadIdx.x;
    const int tx = t & 15;
    const int ty = t >> 4;

    unsigned long long acc[4][2];
#pragma unroll
    for (int i = 0; i < 4; i++) { acc[i][0] = 0ull; acc[i][1] = 0ull; }

    const int rowA = t >> 2;
    const int kqA  = t & 3;
    const int kkW  = t >> 3;
    const int nqW  = t & 7;

    float4 a0 = *(const float4*)&A[(bm + rowA) * H_ + kqA * 4];
    float4 a1 = *(const float4*)&A[(bm + rowA + 32) * H_ + kqA * 4];
    float4 wv = *(const float4*)&W[kkW * H_ + bn + nqW * 4];

    for (int k0 = 0; k0 < H_; k0 += 16) {
        As[kqA * 4 + 0][rowA] = a0.x;
        As[kqA * 4 + 1][rowA] = a0.y;
        As[kqA * 4 + 2][rowA] = a0.z;
        As[kqA * 4 + 3][rowA] = a0.w;
        As[kqA * 4 + 0][rowA + 32] = a1.x;
        As[kqA * 4 + 1][rowA + 32] = a1.y;
        As[kqA * 4 + 2][rowA + 32] = a1.z;
        As[kqA * 4 + 3][rowA + 32] = a1.w;
        *(float4*)&Ws[kkW][nqW * 4] = wv;
        __syncthreads();

        if (k0 + 16 < H_) {
            a0 = *(const float4*)&A[(bm + rowA) * H_ + k0 + 16 + kqA * 4];
            a1 = *(const float4*)&A[(bm + rowA + 32) * H_ + k0 + 16 + kqA * 4];
            wv = *(const float4*)&W[(k0 + 16 + kkW) * H_ + bn + nqW * 4];
        }

#pragma unroll
        for (int k = 0; k < 16; k++) {
            ulonglong2 aP = *(const ulonglong2*)&As[k][ty * 8];
            ulonglong2 aQ = *(const ulonglong2*)&As[k][ty * 8 + 4];
            float2 bv = *(const float2*)&Ws[k][tx * 2];
            unsigned long long b0 = rep2(bv.x);
            unsigned long long b1 = rep2(bv.y);
            ffma2(acc[0][0], aP.x, b0);  ffma2(acc[0][1], aP.x, b1);
            ffma2(acc[1][0], aP.y, b0);  ffma2(acc[1][1], aP.y, b1);
            ffma2(acc[2][0], aQ.x, b0);  ffma2(acc[2][1], aQ.x, b1);
            ffma2(acc[3][0], aQ.y, b0);  ffma2(acc[3][1], aQ.y, b1);
        }
        __syncthreads();
    }

#pragma unroll
    for (int i2 = 0; i2 < 4; i2++) {
        float l0, h0f, l1, h1f;
        unpk2(acc[i2][0], l0, h0f);
        unpk2(acc[i2][1], l1, h1f);
        float2 r0 = {l0, l1};
        float2 r1 = {h0f, h1f};
        *(float2*)&P[(bm + ty * 8 + i2 * 2    ) * H_ + bn + tx * 2] = r0;
        *(float2*)&P[(bm + ty * 8 + i2 * 2 + 1) * H_ + bn + tx * 2] = r1;
    }
}

// ---------------------------------------------------------------------------
// Score kernel, HFMA2 edition: inner loop has ZERO F2F conversions.
// acc_h2 (f16x2) accumulates 8 V*tanh terms, then is folded into an f32
// accumulator (2 F2F per 8 h-pairs instead of 2 per h-pair).
// dp and V interleaved in one uint2 -> single LDS.64 broadcast per h-pair.
// Grid: (TE/32, TD/8, B) = 2048 blocks, 256 threads.
// ---------------------------------------------------------------------------
__global__ __launch_bounds__(256) void score_kernel(const float* __restrict__ V)
{
    __shared__ unsigned sET2[32][33];    // 4.2 KB: [h-pair][e] ep f16x2
    __shared__ uint2 sdv[8][128];        // 8 KB: {dp f16x2, V f16x2} per row

    const int t    = threadIdx.x;
    const int lane = t & 31;
    const int w    = t >> 5;
    const int b    = blockIdx.z;
    const int d0   = blockIdx.y * 8;
    const int e0   = blockIdx.x * 32;

    // Stage dp rows + V, interleaved as f16x2 pairs.
    {
        const float4* dpsrc = (const float4*)(g_dp + (b * TD_ + d0) * H_);
        const float4* vsrc  = (const float4*)V;
#pragma unroll
        for (int i = 0; i < 2; i++) {
            int idx = t + i * 256;               // 0..511
            int row = idx >> 6, colq = idx & 63;
            float4 dv = dpsrc[row * 64 + colq];
            float4 vv = vsrc[colq];
            uint2 p0 = {packh2(dv.x, dv.y), packh2(vv.x, vv.y)};
            uint2 p1 = {packh2(dv.z, dv.w), packh2(vv.z, vv.w)};
            sdv[row][colq * 2]     = p0;
            sdv[row][colq * 2 + 1] = p1;
        }
    }

    const float* ep = g_ep + b * TE_ * H_;
    float acc = 0.f;

    for (int ht = 0; ht < 4; ++ht) {
        __syncthreads();                         // covers sdv staging on iter 0
        // Stage sET2: 32 e-rows x 64 h -> 32 h-pairs x 32 e (transposed)
#pragma unroll
        for (int i = 0; i < 2; i++) {
            int idx = t + i * 256;               // 0..511
            int e_row = idx >> 4, hq = idx & 15;
            float4 v = *(const float4*)&ep[(e0 + e_row) * H_ + ht * 64 + hq * 4];
            sET2[hq * 2    ][e_row] = packh2(v.x, v.y);
            sET2[hq * 2 + 1][e_row] = packh2(v.z, v.w);
        }
        __syncthreads();

        const uint2* dvrow = &sdv[w][ht * 32];
#pragma unroll
        for (int blk = 0; blk < 4; ++blk) {      // 4 blocks of 8 h-pairs
            __half2 acch = __floats2half2_rn(0.f, 0.f);
#pragma unroll
            for (int j = 0; j < 8; ++j) {
                const int hp = blk * 8 + j;
                unsigned ep2 = sET2[hp][lane];
                uint2 dv = dvrow[hp];
                __half2 arg = __hadd2(*(__half2*)&ep2, *(__half2*)&dv.x);
                __half2 th = tanh2_fast(arg);
                acch = __hfma2(th, *(__half2*)&dv.y, acch);
            }
            float2 f = __half22float2(acch);
            acc += f.x + f.y;
        }
    }

    g_score[(b * TD_ + d0 + w) * TE_ + e0 + lane] = acc;
}

// ---------------------------------------------------------------------------
// Softmax: normalizes g_score in place and writes the weights output.
// Grid: 128 blocks x 8 warps = 1024 rows.
// ---------------------------------------------------------------------------
__global__ __launch_bounds__(256) void softmax_kernel(float* __restrict__ out)
{
    const int t    = threadIdx.x;
    const int lane = t & 31;
    const int w    = t >> 5;
    const int row  = blockIdx.x * 8 + w;

    float4* srow = (float4*)(g_score + row * TE_);
    float4 v[4];
    float m = -1e30f;
#pragma unroll
    for (int i = 0; i < 4; i++) {
        v[i] = srow[lane + 32 * i];
        m = fmaxf(m, fmaxf(fmaxf(v[i].x, v[i].y), fmaxf(v[i].z, v[i].w)));
    }
#pragma unroll
    for (int o = 16; o > 0; o >>= 1)
        m = fmaxf(m, __shfl_xor_sync(0xffffffffu, m, o));
    float sum = 0.f;
#pragma unroll
    for (int i = 0; i < 4; i++) {
        v[i].x = __expf(v[i].x - m);
        v[i].y = __expf(v[i].y - m);
        v[i].z = __expf(v[i].z - m);
        v[i].w = __expf(v[i].w - m);
        sum += v[i].x + v[i].y + v[i].z + v[i].w;
    }
#pragma unroll
    for (int o = 16; o > 0; o >>= 1)
        sum += __shfl_xor_sync(0xffffffffu, sum, o);
    const float inv = __fdividef(1.f, sum);
    float4* gout = (float4*)(out + (size_t)B_ * TD_ * H_ + row * TE_);
#pragma unroll
    for (int i = 0; i < 4; i++) {
        v[i].x *= inv; v[i].y *= inv; v[i].z *= inv; v[i].w *= inv;
        srow[lane + 32 * i] = v[i];
        gout[lane + 32 * i] = v[i];
    }
}

// ---------------------------------------------------------------------------
// Context partials (measured-best R6/R9 version).
// Grid: ((H/64)*ESPLIT, TD/32, B) = (16, 4, 8) = 512 blocks, 256 threads.
// ---------------------------------------------------------------------------
__global__ __launch_bounds__(256) void ctx_part_kernel(
    const float* __restrict__ enc)
{
    __shared__ float sE[128][64];    // 32 KB: enc slab [e][h]
    __shared__ float sWt[32][128];   // 16 KB: weights slab [d][e]

    const int t    = threadIdx.x;
    const int lane = t & 31;
    const int w    = t >> 5;
    const int b    = blockIdx.z;
    const int d0   = blockIdx.y * 32;
    const int hq   = blockIdx.x & 3;        // h tile
    const int es   = blockIdx.x >> 2;       // e split (0..3)
    const int h0   = hq * 64;
    const int e0   = es * 128;

    const float* enc_b = enc + b * TE_ * H_;
    const float* wbase = g_score + (b * TD_ + d0) * TE_;

    // stage sE: 128 e-rows x 64 h
#pragma unroll
    for (int i = 0; i < 8; i++) {
        int idx = t + i * 256;               // 2048 float4 slots
        int row = idx >> 4, col = (idx & 15) * 4;
        *(float4*)&sE[row][col] =
            *(const float4*)&enc_b[(e0 + row) * H_ + h0 + col];
    }
    // stage sWt: 32 d-rows x 128 e
#pragma unroll
    for (int i = 0; i < 4; i++) {
        int idx = t + i * 256;               // 1024 float4 slots
        int row = idx >> 5, col = (idx & 31) * 4;
        *(float4*)&sWt[row][col] =
            *(const float4*)&wbase[row * TE_ + e0 + col];
    }
    __syncthreads();

    unsigned long long acc[4] = {0ull, 0ull, 0ull, 0ull};

#pragma unroll 2
    for (int e4 = 0; e4 < 32; ++e4) {
        float4 wr0 = *(const float4*)&sWt[w     ][e4 * 4];
        float4 wr1 = *(const float4*)&sWt[w +  8][e4 * 4];
        float4 wr2 = *(const float4*)&sWt[w + 16][e4 * 4];
        float4 wr3 = *(const float4*)&sWt[w + 24][e4 * 4];
        const float* f0 = (const float*)&wr0;
        const float* f1 = (const float*)&wr1;
        const float* f2 = (const float*)&wr2;
        const float* f3 = (const float*)&wr3;
#pragma unroll
        for (int j = 0; j < 4; j++) {
            unsigned long long ev =
                *(const unsigned long long*)&sE[e4 * 4 + j][lane * 2];
            ffma2(acc[0], rep2(f0[j]), ev);
            ffma2(acc[1], rep2(f1[j]), ev);
            ffma2(acc[2], rep2(f2[j]), ev);
            ffma2(acc[3], rep2(f3[j]), ev);
        }
    }

#pragma unroll
    for (int r = 0; r < 4; r++) {
        float lo, hi;
        unpk2(acc[r], lo, hi);
        float2 o = {lo, hi};
        *(float2*)&g_part[es][(b * TD_ + d0 + w + 8 * r) * H_ + h0 + lane * 2] = o;
    }
}

// ---------------------------------------------------------------------------
// Combine: out = (p0+p1)+(p2+p3), fixed order (deterministic).
// Grid 512 x 128 threads (even SM spread, 65536 float4 lanes).
// ---------------------------------------------------------------------------
__global__ __launch_bounds__(128) void combine_kernel(float* __restrict__ out)
{
    const int i = blockIdx.x * 128 + threadIdx.x;   // float4 index
    const float4 p0 = ((const float4*)g_part[0])[i];
    const float4 p1 = ((const float4*)g_part[1])[i];
    const float4 p2 = ((const float4*)g_part[2])[i];
    const float4 p3 = ((const float4*)g_part[3])[i];
    float4 o;
    o.x = (p0.x + p1.x) + (p2.x + p3.x);
    o.y = (p0.y + p1.y) + (p2.y + p3.y);
    o.z = (p0.z + p1.z) + (p2.z + p3.z);
    o.w = (p0.w + p1.w) + (p2.w + p3.w);
    ((float4*)out)[i] = o;
}

// ---------------------------------------------------------------------------
extern "C" void kernel_launch(void* const* d_in, const int* in_sizes, int n_in,
                              void* d_out, int out_size)
{
    const float* enc = (const float*)d_in[0];   // [B,TE,H]
    const float* dec = (const float*)d_in[1];   // [B,TD,H]
    const float* Wa  = (const float*)d_in[2];   // [H,H]
    const float* Ua  = (const float*)d_in[3];   // [H,H]
    const float* Va  = (const float*)d_in[4];   // [H,1]
    float* out = (float*)d_out;                 // context [B,TD,H] then weights [B,TD,TE]

    proj_kernel<<<dim3(640), 128>>>(enc, dec, Wa, Ua);
    score_kernel<<<dim3(TE_ / 32, TD_ / 8, B_), 256>>>(Va);
    softmax_kernel<<<dim3(128), 256>>>(out);
    ctx_part_kernel<<<dim3((H_ / 64) * ESPLIT, TD_ / 32, B_), 256>>>(enc);
    combine_kernel<<<dim3(512), 128>>>(out);
}